// round 2
// baseline (speedup 1.0000x reference)
#include <cuda_runtime.h>
#include <cuda_bf16.h>
#include <math_constants.h>

// Problem constants
#define PB 2
#define PS 2048
#define PE 1024
#define PH 16
#define PHD 64
#define PBH (PB * PH)        // 32
#define PM (PB * PS)         // 4096 rows for all projection GEMMs

// ---------------------------------------------------------------------------
// Scratch (no cudaMalloc allowed)
// ---------------------------------------------------------------------------
__device__ float g_qp[PM * PE];
__device__ float g_kp[PM * PE];
__device__ float g_vp[PM * PE];
__device__ float g_ao[PM * PE];

// ---------------------------------------------------------------------------
// SGEMM: C[M,N] = A[M,K] @ B[N,K]^T   (torch Linear, bias-free)
// 128x128 block tile, K-tile 8, 256 threads, 8x8 per thread.
// Global loads for tile k+1 are prefetched into registers during compute of k.
// ---------------------------------------------------------------------------
#define TM 128
#define TN 128
#define TK 8

__global__ __launch_bounds__(256, 2)
void sgemm_tn(const float* __restrict__ A, const float* __restrict__ B,
              float* __restrict__ C, int M, int N, int K)
{
    __shared__ float As[TK][TM];
    __shared__ float Bs[TK][TN];

    const int tid = threadIdx.x;
    const int bm = blockIdx.y * TM;
    const int bn = blockIdx.x * TN;
    const int tm = (tid >> 4) * 8;   // 0..120
    const int tn = (tid & 15) * 8;   // 0..120

    // loader: each thread loads one float4 of A and one of B per K-tile
    const int lr = tid >> 1;          // 0..127 (row within tile)
    const int lc = (tid & 1) * 4;     // 0 or 4 (k offset)

    float acc[8][8];
#pragma unroll
    for (int i = 0; i < 8; i++)
#pragma unroll
        for (int j = 0; j < 8; j++) acc[i][j] = 0.f;

    const float* Ap = A + (size_t)(bm + lr) * K + lc;
    const float* Bp = B + (size_t)(bn + lr) * K + lc;

    // prefetch tile 0
    float4 a4 = *(const float4*)(Ap);
    float4 b4 = *(const float4*)(Bp);

    for (int k0 = 0; k0 < K; k0 += TK) {
        As[lc + 0][lr] = a4.x; As[lc + 1][lr] = a4.y;
        As[lc + 2][lr] = a4.z; As[lc + 3][lr] = a4.w;
        Bs[lc + 0][lr] = b4.x; Bs[lc + 1][lr] = b4.y;
        Bs[lc + 2][lr] = b4.z; Bs[lc + 3][lr] = b4.w;
        __syncthreads();

        // prefetch next tile while computing this one
        if (k0 + TK < K) {
            a4 = *(const float4*)(Ap + k0 + TK);
            b4 = *(const float4*)(Bp + k0 + TK);
        }

#pragma unroll
        for (int k = 0; k < TK; k++) {
            float4 ra0 = *(const float4*)&As[k][tm];
            float4 ra1 = *(const float4*)&As[k][tm + 4];
            float4 rb0 = *(const float4*)&Bs[k][tn];
            float4 rb1 = *(const float4*)&Bs[k][tn + 4];
            float ra[8] = {ra0.x, ra0.y, ra0.z, ra0.w, ra1.x, ra1.y, ra1.z, ra1.w};
            float rb[8] = {rb0.x, rb0.y, rb0.z, rb0.w, rb1.x, rb1.y, rb1.z, rb1.w};
#pragma unroll
            for (int i = 0; i < 8; i++)
#pragma unroll
                for (int j = 0; j < 8; j++)
                    acc[i][j] = fmaf(ra[i], rb[j], acc[i][j]);
        }
        __syncthreads();
    }

#pragma unroll
    for (int i = 0; i < 8; i++) {
        float* Cp = C + (size_t)(bm + tm + i) * N + bn + tn;
        *(float4*)(Cp)     = make_float4(acc[i][0], acc[i][1], acc[i][2], acc[i][3]);
        *(float4*)(Cp + 4) = make_float4(acc[i][4], acc[i][5], acc[i][6], acc[i][7]);
    }
}

// ---------------------------------------------------------------------------
// Flash attention (fp32, online softmax, causal tile skipping)
// Q/K/V/O viewed as [BH=32][S=2048][64] contiguous (reshape is a pure
// reinterpret in the reference, so no transpose is needed anywhere).
// Block: 64 q-rows; loops over 64-row k/v tiles. 256 threads, 4x4 micro-tile.
// Dynamic smem: Qs[64][64] + KVs[64][65] + Ps[64][65]
// ---------------------------------------------------------------------------
#define AT_PAD 65
#define FLASH_SMEM ((64 * 64 + 64 * AT_PAD + 64 * AT_PAD) * 4)

__global__ __launch_bounds__(256, 4)
void flash_attn(const float* __restrict__ Q, const float* __restrict__ K,
                const float* __restrict__ V, float* __restrict__ O,
                const int* __restrict__ maskflag)
{
    extern __shared__ float sm[];
    float* Qs  = sm;                      // 64*64
    float* KVs = sm + 64 * 64;            // 64*65 (K, then reused for V)
    float* Ps  = KVs + 64 * AT_PAD;       // 64*65

    const int tid = threadIdx.x;
    const int bh  = blockIdx.y;
    const int m0  = blockIdx.x * 64;

    const float* Qb = Q + (size_t)bh * PS * PHD;
    const float* Kb = K + (size_t)bh * PS * PHD;
    const float* Vb = V + (size_t)bh * PS * PHD;
    float*       Ob = O + (size_t)bh * PS * PHD + (size_t)m0 * PHD;

    const int tm = (tid >> 4) * 4;   // row group
    const int tn = (tid & 15) * 4;   // col / d group

    // load Q tile (64x64) with float4
    for (int t = tid; t < 1024; t += 256) {
        int r = t >> 4, c4 = (t & 15) << 2;
        *(float4*)&Qs[r * 64 + c4] = *(const float4*)(Qb + (size_t)(m0 + r) * PHD + c4);
    }

    const bool causal = (*maskflag != 0);
    const int ntiles = causal ? (blockIdx.x + 1) : (PS / 64);

    float mrow[4], lrow[4], o[4][4];
#pragma unroll
    for (int i = 0; i < 4; i++) {
        mrow[i] = -1e30f; lrow[i] = 0.f;
#pragma unroll
        for (int j = 0; j < 4; j++) o[i][j] = 0.f;
    }
    __syncthreads();

    for (int kt = 0; kt < ntiles; kt++) {
        const int n0 = kt * 64;

        // load K tile into KVs[n][d] (padded rows)
        for (int t = tid; t < 1024; t += 256) {
            int r = t >> 4, c4 = (t & 15) << 2;
            float4 x = *(const float4*)(Kb + (size_t)(n0 + r) * PHD + c4);
            float* dst = &KVs[r * AT_PAD + c4];
            dst[0] = x.x; dst[1] = x.y; dst[2] = x.z; dst[3] = x.w;
        }
        __syncthreads();

        // scores S = scale * Q K^T  (4x4 per thread)
        float s[4][4];
#pragma unroll
        for (int i = 0; i < 4; i++)
#pragma unroll
            for (int j = 0; j < 4; j++) s[i][j] = 0.f;

#pragma unroll 4
        for (int d = 0; d < 64; d++) {
            float qf[4], kf[4];
#pragma unroll
            for (int i = 0; i < 4; i++) qf[i] = Qs[(tm + i) * 64 + d];
#pragma unroll
            for (int j = 0; j < 4; j++) kf[j] = KVs[(tn + j) * AT_PAD + d];
#pragma unroll
            for (int i = 0; i < 4; i++)
#pragma unroll
                for (int j = 0; j < 4; j++)
                    s[i][j] = fmaf(qf[i], kf[j], s[i][j]);
        }

        const float scale = 0.125f;  // 1/sqrt(64)
#pragma unroll
        for (int i = 0; i < 4; i++)
#pragma unroll
            for (int j = 0; j < 4; j++) {
                s[i][j] *= scale;
                if (causal && (n0 + tn + j > m0 + tm + i)) s[i][j] = -1e30f;
            }

        // online softmax per row (16-lane group reduction)
#pragma unroll
        for (int i = 0; i < 4; i++) {
            float pm = s[i][0];
#pragma unroll
            for (int j = 1; j < 4; j++) pm = fmaxf(pm, s[i][j]);
#pragma unroll
            for (int off = 8; off >= 1; off >>= 1)
                pm = fmaxf(pm, __shfl_xor_sync(0xffffffffu, pm, off));
            float mnew = fmaxf(mrow[i], pm);
            float alpha = __expf(mrow[i] - mnew);
            float psum = 0.f;
#pragma unroll
            for (int j = 0; j < 4; j++) {
                float p = __expf(s[i][j] - mnew);
                Ps[(tm + i) * AT_PAD + tn + j] = p;
                psum += p;
            }
#pragma unroll
            for (int off = 8; off >= 1; off >>= 1)
                psum += __shfl_xor_sync(0xffffffffu, psum, off);
            lrow[i] = lrow[i] * alpha + psum;
            mrow[i] = mnew;
#pragma unroll
            for (int j = 0; j < 4; j++) o[i][j] *= alpha;
        }
        __syncthreads();   // Ps visible; KVs (K) fully consumed

        // load V tile into KVs[n][d]
        for (int t = tid; t < 1024; t += 256) {
            int r = t >> 4, c4 = (t & 15) << 2;
            float4 x = *(const float4*)(Vb + (size_t)(n0 + r) * PHD + c4);
            float* dst = &KVs[r * AT_PAD + c4];
            dst[0] = x.x; dst[1] = x.y; dst[2] = x.z; dst[3] = x.w;
        }
        __syncthreads();

        // O += P @ V
#pragma unroll 4
        for (int n = 0; n < 64; n++) {
            float pf[4], vf[4];
#pragma unroll
            for (int i = 0; i < 4; i++) pf[i] = Ps[(tm + i) * AT_PAD + n];
#pragma unroll
            for (int j = 0; j < 4; j++) vf[j] = KVs[n * AT_PAD + tn + j];
#pragma unroll
            for (int i = 0; i < 4; i++)
#pragma unroll
                for (int j = 0; j < 4; j++)
                    o[i][j] = fmaf(pf[i], vf[j], o[i][j]);
        }
        __syncthreads();   // done with Ps / KVs for this tile
    }

    // epilogue: normalize and store
#pragma unroll
    for (int i = 0; i < 4; i++) {
        float inv = 1.0f / lrow[i];
#pragma unroll
        for (int j = 0; j < 4; j++)
            Ob[(size_t)(tm + i) * PHD + tn + j] = o[i][j] * inv;
    }
}

// ---------------------------------------------------------------------------
// Launch
// ---------------------------------------------------------------------------
extern "C" void kernel_launch(void* const* d_in, const int* in_sizes, int n_in,
                              void* d_out, int out_size)
{
    const float* q  = (const float*)d_in[0];
    const float* k  = (const float*)d_in[1];
    const float* v  = (const float*)d_in[2];
    const float* wq = (const float*)d_in[3];
    const float* wk = (const float*)d_in[4];
    const float* wv = (const float*)d_in[5];
    const float* wo = (const float*)d_in[6];
    const int*   am = (const int*)d_in[7];
    float* out = (float*)d_out;

    float *qp, *kp, *vp, *ao;
    cudaGetSymbolAddress((void**)&qp, g_qp);
    cudaGetSymbolAddress((void**)&kp, g_kp);
    cudaGetSymbolAddress((void**)&vp, g_vp);
    cudaGetSymbolAddress((void**)&ao, g_ao);

    cudaFuncSetAttribute(flash_attn, cudaFuncAttributeMaxDynamicSharedMemorySize,
                         FLASH_SMEM);

    dim3 gGemm(PE / TN, PM / TM);   // (8, 32)
    sgemm_tn<<<gGemm, 256>>>(q, wq, qp, PM, PE, PE);
    sgemm_tn<<<gGemm, 256>>>(k, wk, kp, PM, PE, PE);
    sgemm_tn<<<gGemm, 256>>>(v, wv, vp, PM, PE, PE);

    dim3 gAttn(PS / 64, PBH);       // (32, 32)
    flash_attn<<<gAttn, 256, FLASH_SMEM>>>(qp, kp, vp, ao, am);

    sgemm_tn<<<gGemm, 256>>>(ao, wo, out, PM, PE, PE);
}

// round 3
// speedup vs baseline: 1.1284x; 1.1284x over previous
#include <cuda_runtime.h>
#include <cuda_bf16.h>
#include <math_constants.h>

// Problem constants
#define PB 2
#define PS 2048
#define PE 1024
#define PH 16
#define PHD 64
#define PBH (PB * PH)        // 32
#define PM (PB * PS)         // 4096 rows for all projection GEMMs

// ---------------------------------------------------------------------------
// Scratch (no cudaMalloc allowed)
// ---------------------------------------------------------------------------
__device__ float g_qp[PM * PE];
__device__ float g_kp[PM * PE];
__device__ float g_vp[PM * PE];
__device__ float g_ao[PM * PE];

// ---------------------------------------------------------------------------
// SGEMM: C[M,N] = A[M,K] @ B[N,K]^T   (torch Linear, bias-free)
// 128x128 block tile, K-tile 16, 256 threads, 8x8 per thread.
// Double-buffered shared memory, register prefetch of the next K-tile.
// ---------------------------------------------------------------------------
#define TM 128
#define TN 128
#define TK 16

__global__ __launch_bounds__(256, 2)
void sgemm_tn(const float* __restrict__ A, const float* __restrict__ B,
              float* __restrict__ C, int M, int N, int K)
{
    __shared__ float As[2][TK][TM];
    __shared__ float Bs[2][TK][TN];

    const int tid = threadIdx.x;
    const int bm = blockIdx.y * TM;
    const int bn = blockIdx.x * TN;
    const int tm = (tid >> 4) * 8;   // 0..120
    const int tn = (tid & 15) * 8;   // 0..120

    // loader: each thread loads 2 float4 of A and 2 of B per K-tile (16 k's)
    const int lr = tid >> 1;          // 0..127 (row within tile)
    const int lc = (tid & 1) * 4;     // 0 or 4 (k offset; +8 for second chunk)

    float acc[8][8];
#pragma unroll
    for (int i = 0; i < 8; i++)
#pragma unroll
        for (int j = 0; j < 8; j++) acc[i][j] = 0.f;

    const float* Ap = A + (size_t)(bm + lr) * K + lc;
    const float* Bp = B + (size_t)(bn + lr) * K + lc;

    // prefetch tile 0 into registers
    float4 pa0 = *(const float4*)(Ap);
    float4 pa1 = *(const float4*)(Ap + 8);
    float4 pb0 = *(const float4*)(Bp);
    float4 pb1 = *(const float4*)(Bp + 8);

    // store tile 0 into buffer 0
    As[0][lc + 0][lr] = pa0.x; As[0][lc + 1][lr] = pa0.y;
    As[0][lc + 2][lr] = pa0.z; As[0][lc + 3][lr] = pa0.w;
    As[0][lc + 8][lr] = pa1.x; As[0][lc + 9][lr] = pa1.y;
    As[0][lc +10][lr] = pa1.z; As[0][lc +11][lr] = pa1.w;
    Bs[0][lc + 0][lr] = pb0.x; Bs[0][lc + 1][lr] = pb0.y;
    Bs[0][lc + 2][lr] = pb0.z; Bs[0][lc + 3][lr] = pb0.w;
    Bs[0][lc + 8][lr] = pb1.x; Bs[0][lc + 9][lr] = pb1.y;
    Bs[0][lc +10][lr] = pb1.z; Bs[0][lc +11][lr] = pb1.w;
    __syncthreads();

    int buf = 0;
    for (int k0 = 0; k0 < K; k0 += TK) {
        const bool more = (k0 + TK < K);
        if (more) {
            pa0 = *(const float4*)(Ap + k0 + TK);
            pa1 = *(const float4*)(Ap + k0 + TK + 8);
            pb0 = *(const float4*)(Bp + k0 + TK);
            pb1 = *(const float4*)(Bp + k0 + TK + 8);
        }

#pragma unroll
        for (int k = 0; k < TK; k++) {
            float4 ra0 = *(const float4*)&As[buf][k][tm];
            float4 ra1 = *(const float4*)&As[buf][k][tm + 4];
            float4 rb0 = *(const float4*)&Bs[buf][k][tn];
            float4 rb1 = *(const float4*)&Bs[buf][k][tn + 4];
            float ra[8] = {ra0.x, ra0.y, ra0.z, ra0.w, ra1.x, ra1.y, ra1.z, ra1.w};
            float rb[8] = {rb0.x, rb0.y, rb0.z, rb0.w, rb1.x, rb1.y, rb1.z, rb1.w};
#pragma unroll
            for (int i = 0; i < 8; i++)
#pragma unroll
                for (int j = 0; j < 8; j++)
                    acc[i][j] = fmaf(ra[i], rb[j], acc[i][j]);
        }

        if (more) {
            const int nb = buf ^ 1;
            As[nb][lc + 0][lr] = pa0.x; As[nb][lc + 1][lr] = pa0.y;
            As[nb][lc + 2][lr] = pa0.z; As[nb][lc + 3][lr] = pa0.w;
            As[nb][lc + 8][lr] = pa1.x; As[nb][lc + 9][lr] = pa1.y;
            As[nb][lc +10][lr] = pa1.z; As[nb][lc +11][lr] = pa1.w;
            Bs[nb][lc + 0][lr] = pb0.x; Bs[nb][lc + 1][lr] = pb0.y;
            Bs[nb][lc + 2][lr] = pb0.z; Bs[nb][lc + 3][lr] = pb0.w;
            Bs[nb][lc + 8][lr] = pb1.x; Bs[nb][lc + 9][lr] = pb1.y;
            Bs[nb][lc +10][lr] = pb1.z; Bs[nb][lc +11][lr] = pb1.w;
            __syncthreads();
            buf = nb;
        }
    }

#pragma unroll
    for (int i = 0; i < 8; i++) {
        float* Cp = C + (size_t)(bm + tm + i) * N + bn + tn;
        *(float4*)(Cp)     = make_float4(acc[i][0], acc[i][1], acc[i][2], acc[i][3]);
        *(float4*)(Cp + 4) = make_float4(acc[i][4], acc[i][5], acc[i][6], acc[i][7]);
    }
}

// ---------------------------------------------------------------------------
// Flash attention (fp32, online softmax, causal tile skipping)
// Q/K/V/O viewed as [BH=32][S=2048][64] contiguous (reshape is a pure
// reinterpret in the reference, so no transpose is needed anywhere).
// Block: 64 q-rows; loops over 64-row k/v tiles. 256 threads, 4x4 micro-tile.
//
// Shared layouts chosen for LDS vectorization / conflict-freedom:
//   QT[d][m]   (pad 64): qf = one broadcast LDS.128 per d
//   Ks[n][d]   (pad 65): kf scalar loads, 16 distinct banks + broadcast
//   Vs[n][d]   (pad 68): vf = one LDS.128 per n
//   Ps[m][n]   (pad 68): P written as STS.128, pf scalar broadcast loads
// ---------------------------------------------------------------------------
#define KPAD 65
#define VPAD 68
#define PPAD 68
#define SM_QT (64 * 64)
#define SM_KS (64 * KPAD)
#define SM_VS (64 * VPAD)
#define SM_PS (64 * PPAD)
#define FLASH_SMEM ((SM_QT + SM_KS + SM_VS + SM_PS) * 4)

__global__ __launch_bounds__(256)
void flash_attn(const float* __restrict__ Q, const float* __restrict__ K,
                const float* __restrict__ V, float* __restrict__ O,
                const int* __restrict__ maskflag)
{
    extern __shared__ float sm[];
    float* QT = sm;                 // [d][m]
    float* Ks = QT + SM_QT;         // [n][d] pad 65
    float* Vs = Ks + SM_KS;         // [n][d] pad 68
    float* Ps = Vs + SM_VS;         // [m][n] pad 68

    const int tid = threadIdx.x;
    const int bh  = blockIdx.y;
    const int m0  = blockIdx.x * 64;

    const float* Qb = Q + (size_t)bh * PS * PHD;
    const float* Kb = K + (size_t)bh * PS * PHD;
    const float* Vb = V + (size_t)bh * PS * PHD;
    float*       Ob = O + (size_t)bh * PS * PHD + (size_t)m0 * PHD;

    const int tm = (tid >> 4) * 4;   // row group
    const int tn = (tid & 15) * 4;   // col / d group

    // load Q tile (64x64) and transpose into QT[d][m] (one-time cost)
    for (int t = tid; t < 1024; t += 256) {
        int r = t >> 4, c4 = (t & 15) << 2;
        float4 x = *(const float4*)(Qb + (size_t)(m0 + r) * PHD + c4);
        QT[(c4 + 0) * 64 + r] = x.x;
        QT[(c4 + 1) * 64 + r] = x.y;
        QT[(c4 + 2) * 64 + r] = x.z;
        QT[(c4 + 3) * 64 + r] = x.w;
    }

    const bool causal = (*maskflag != 0);
    const int ntiles = causal ? (blockIdx.x + 1) : (PS / 64);

    float mrow[4], lrow[4], o[4][4];
#pragma unroll
    for (int i = 0; i < 4; i++) {
        mrow[i] = -1e30f; lrow[i] = 0.f;
#pragma unroll
        for (int j = 0; j < 4; j++) o[i][j] = 0.f;
    }

    for (int kt = 0; kt < ntiles; kt++) {
        const int n0 = kt * 64;

        // load K and V tiles together (more MLP)
        for (int t = tid; t < 1024; t += 256) {
            int r = t >> 4, c4 = (t & 15) << 2;
            float4 xk = *(const float4*)(Kb + (size_t)(n0 + r) * PHD + c4);
            float* kd = &Ks[r * KPAD + c4];
            kd[0] = xk.x; kd[1] = xk.y; kd[2] = xk.z; kd[3] = xk.w;
            float4 xv = *(const float4*)(Vb + (size_t)(n0 + r) * PHD + c4);
            *(float4*)&Vs[r * VPAD + c4] = xv;
        }
        __syncthreads();   // K/V ready (and QT on first iteration)

        // scores S = scale * Q K^T  (4x4 per thread)
        float s[4][4];
#pragma unroll
        for (int i = 0; i < 4; i++)
#pragma unroll
            for (int j = 0; j < 4; j++) s[i][j] = 0.f;

#pragma unroll 8
        for (int d = 0; d < 64; d++) {
            float4 q4 = *(const float4*)&QT[d * 64 + tm];
            float qf[4] = {q4.x, q4.y, q4.z, q4.w};
            float kf[4];
#pragma unroll
            for (int j = 0; j < 4; j++) kf[j] = Ks[(tn + j) * KPAD + d];
#pragma unroll
            for (int i = 0; i < 4; i++)
#pragma unroll
                for (int j = 0; j < 4; j++)
                    s[i][j] = fmaf(qf[i], kf[j], s[i][j]);
        }

        const float scale = 0.125f;  // 1/sqrt(64)
#pragma unroll
        for (int i = 0; i < 4; i++)
#pragma unroll
            for (int j = 0; j < 4; j++) {
                s[i][j] *= scale;
                if (causal && (n0 + tn + j > m0 + tm + i)) s[i][j] = -1e30f;
            }

        // online softmax per row (16-lane group reduction)
#pragma unroll
        for (int i = 0; i < 4; i++) {
            float pm = s[i][0];
#pragma unroll
            for (int j = 1; j < 4; j++) pm = fmaxf(pm, s[i][j]);
#pragma unroll
            for (int off = 8; off >= 1; off >>= 1)
                pm = fmaxf(pm, __shfl_xor_sync(0xffffffffu, pm, off));
            float mnew = fmaxf(mrow[i], pm);
            float alpha = __expf(mrow[i] - mnew);
            float p0 = __expf(s[i][0] - mnew);
            float p1 = __expf(s[i][1] - mnew);
            float p2 = __expf(s[i][2] - mnew);
            float p3 = __expf(s[i][3] - mnew);
            *(float4*)&Ps[(tm + i) * PPAD + tn] = make_float4(p0, p1, p2, p3);
            float psum = (p0 + p1) + (p2 + p3);
#pragma unroll
            for (int off = 8; off >= 1; off >>= 1)
                psum += __shfl_xor_sync(0xffffffffu, psum, off);
            lrow[i] = lrow[i] * alpha + psum;
            mrow[i] = mnew;
#pragma unroll
            for (int j = 0; j < 4; j++) o[i][j] *= alpha;
        }
        __syncthreads();   // Ps visible

        // O += P @ V
#pragma unroll 8
        for (int n = 0; n < 64; n++) {
            float pf[4];
#pragma unroll
            for (int i = 0; i < 4; i++) pf[i] = Ps[(tm + i) * PPAD + n];
            float4 v4 = *(const float4*)&Vs[n * VPAD + tn];
            float vf[4] = {v4.x, v4.y, v4.z, v4.w};
#pragma unroll
            for (int i = 0; i < 4; i++)
#pragma unroll
                for (int j = 0; j < 4; j++)
                    o[i][j] = fmaf(pf[i], vf[j], o[i][j]);
        }
        __syncthreads();   // protect Ks/Vs/Ps before next tile overwrites
    }

    // epilogue: normalize and store
#pragma unroll
    for (int i = 0; i < 4; i++) {
        float inv = 1.0f / lrow[i];
#pragma unroll
        for (int j = 0; j < 4; j++)
            Ob[(size_t)(tm + i) * PHD + tn + j] = o[i][j] * inv;
    }
}

// ---------------------------------------------------------------------------
// Launch
// ---------------------------------------------------------------------------
extern "C" void kernel_launch(void* const* d_in, const int* in_sizes, int n_in,
                              void* d_out, int out_size)
{
    const float* q  = (const float*)d_in[0];
    const float* k  = (const float*)d_in[1];
    const float* v  = (const float*)d_in[2];
    const float* wq = (const float*)d_in[3];
    const float* wk = (const float*)d_in[4];
    const float* wv = (const float*)d_in[5];
    const float* wo = (const float*)d_in[6];
    const int*   am = (const int*)d_in[7];
    float* out = (float*)d_out;

    float *qp, *kp, *vp, *ao;
    cudaGetSymbolAddress((void**)&qp, g_qp);
    cudaGetSymbolAddress((void**)&kp, g_kp);
    cudaGetSymbolAddress((void**)&vp, g_vp);
    cudaGetSymbolAddress((void**)&ao, g_ao);

    cudaFuncSetAttribute(flash_attn, cudaFuncAttributeMaxDynamicSharedMemorySize,
                         FLASH_SMEM);

    dim3 gGemm(PE / TN, PM / TM);   // (8, 32)
    sgemm_tn<<<gGemm, 256>>>(q, wq, qp, PM, PE, PE);
    sgemm_tn<<<gGemm, 256>>>(k, wk, kp, PM, PE, PE);
    sgemm_tn<<<gGemm, 256>>>(v, wv, vp, PM, PE, PE);

    dim3 gAttn(PS / 64, PBH);       // (32, 32)
    flash_attn<<<gAttn, 256, FLASH_SMEM>>>(qp, kp, vp, ao, am);

    sgemm_tn<<<gGemm, 256>>>(ao, wo, out, PM, PE, PE);
}

// round 4
// speedup vs baseline: 1.1345x; 1.0054x over previous
#include <cuda_runtime.h>
#include <cuda_bf16.h>
#include <math_constants.h>

// Problem constants
#define PB 2
#define PS 2048
#define PE 1024
#define PH 16
#define PHD 64
#define PBH (PB * PH)        // 32
#define PM (PB * PS)         // 4096 rows for all projection GEMMs

typedef unsigned long long ull;

// ---------------------------------------------------------------------------
// f32x2 packed-math helpers (Blackwell FFMA2 path; ptxas never auto-fuses)
// ---------------------------------------------------------------------------
__device__ __forceinline__ ull pk2(float x, float y) {
    ull r; asm("mov.b64 %0, {%1, %2};" : "=l"(r) : "f"(x), "f"(y)); return r;
}
__device__ __forceinline__ void upk2(ull v, float& x, float& y) {
    asm("mov.b64 {%0, %1}, %2;" : "=f"(x), "=f"(y) : "l"(v));
}
__device__ __forceinline__ ull ffma2(ull a, ull b, ull c) {
    ull d; asm("fma.rn.f32x2 %0, %1, %2, %3;" : "=l"(d) : "l"(a), "l"(b), "l"(c)); return d;
}
__device__ __forceinline__ ull fmul2(ull a, ull b) {
    ull d; asm("mul.rn.f32x2 %0, %1, %2;" : "=l"(d) : "l"(a), "l"(b)); return d;
}

// ---------------------------------------------------------------------------
// Scratch (no cudaMalloc allowed)
// ---------------------------------------------------------------------------
__device__ float g_qp[PM * PE];
__device__ float g_kp[PM * PE];
__device__ float g_vp[PM * PE];
__device__ float g_ao[PM * PE];

// ---------------------------------------------------------------------------
// SGEMM: C[M,N] = A[M,K] @ B[N,K]^T   (torch Linear, bias-free)
// 128x128 block tile, K-tile 16, 256 threads, 8x8 per thread.
// Double-buffered smem; accumulation in packed f32x2 (pairs over m).
// ---------------------------------------------------------------------------
#define TM 128
#define TN 128
#define TK 16

__global__ __launch_bounds__(256, 2)
void sgemm_tn(const float* __restrict__ A, const float* __restrict__ B,
              float* __restrict__ C, int M, int N, int K)
{
    __shared__ float As[2][TK][TM];
    __shared__ float Bs[2][TK][TN];

    const int tid = threadIdx.x;
    const int bm = blockIdx.y * TM;
    const int bn = blockIdx.x * TN;
    const int tm = (tid >> 4) * 8;   // 0..120
    const int tn = (tid & 15) * 8;   // 0..120

    const int lr = tid >> 1;          // 0..127 (row within tile)
    const int lc = (tid & 1) * 4;     // 0 or 4 (k offset; +8 for second chunk)

    ull acc2[4][8];
#pragma unroll
    for (int ip = 0; ip < 4; ip++)
#pragma unroll
        for (int j = 0; j < 8; j++) acc2[ip][j] = 0ULL;

    const float* Ap = A + (size_t)(bm + lr) * K + lc;
    const float* Bp = B + (size_t)(bn + lr) * K + lc;

    // prefetch tile 0 into registers
    float4 pa0 = *(const float4*)(Ap);
    float4 pa1 = *(const float4*)(Ap + 8);
    float4 pb0 = *(const float4*)(Bp);
    float4 pb1 = *(const float4*)(Bp + 8);

    As[0][lc + 0][lr] = pa0.x; As[0][lc + 1][lr] = pa0.y;
    As[0][lc + 2][lr] = pa0.z; As[0][lc + 3][lr] = pa0.w;
    As[0][lc + 8][lr] = pa1.x; As[0][lc + 9][lr] = pa1.y;
    As[0][lc +10][lr] = pa1.z; As[0][lc +11][lr] = pa1.w;
    Bs[0][lc + 0][lr] = pb0.x; Bs[0][lc + 1][lr] = pb0.y;
    Bs[0][lc + 2][lr] = pb0.z; Bs[0][lc + 3][lr] = pb0.w;
    Bs[0][lc + 8][lr] = pb1.x; Bs[0][lc + 9][lr] = pb1.y;
    Bs[0][lc +10][lr] = pb1.z; Bs[0][lc +11][lr] = pb1.w;
    __syncthreads();

    int buf = 0;
    for (int k0 = 0; k0 < K; k0 += TK) {
        const bool more = (k0 + TK < K);
        if (more) {
            pa0 = *(const float4*)(Ap + k0 + TK);
            pa1 = *(const float4*)(Ap + k0 + TK + 8);
            pb0 = *(const float4*)(Bp + k0 + TK);
            pb1 = *(const float4*)(Bp + k0 + TK + 8);
        }

#pragma unroll
        for (int k = 0; k < TK; k++) {
            ull a2[4];
            a2[0] = *(const ull*)&As[buf][k][tm + 0];
            a2[1] = *(const ull*)&As[buf][k][tm + 2];
            a2[2] = *(const ull*)&As[buf][k][tm + 4];
            a2[3] = *(const ull*)&As[buf][k][tm + 6];
            float4 rb0 = *(const float4*)&Bs[buf][k][tn];
            float4 rb1 = *(const float4*)&Bs[buf][k][tn + 4];
            ull b2[8];
            b2[0] = pk2(rb0.x, rb0.x); b2[1] = pk2(rb0.y, rb0.y);
            b2[2] = pk2(rb0.z, rb0.z); b2[3] = pk2(rb0.w, rb0.w);
            b2[4] = pk2(rb1.x, rb1.x); b2[5] = pk2(rb1.y, rb1.y);
            b2[6] = pk2(rb1.z, rb1.z); b2[7] = pk2(rb1.w, rb1.w);
#pragma unroll
            for (int ip = 0; ip < 4; ip++)
#pragma unroll
                for (int j = 0; j < 8; j++)
                    acc2[ip][j] = ffma2(a2[ip], b2[j], acc2[ip][j]);
        }

        if (more) {
            const int nb = buf ^ 1;
            As[nb][lc + 0][lr] = pa0.x; As[nb][lc + 1][lr] = pa0.y;
            As[nb][lc + 2][lr] = pa0.z; As[nb][lc + 3][lr] = pa0.w;
            As[nb][lc + 8][lr] = pa1.x; As[nb][lc + 9][lr] = pa1.y;
            As[nb][lc +10][lr] = pa1.z; As[nb][lc +11][lr] = pa1.w;
            Bs[nb][lc + 0][lr] = pb0.x; Bs[nb][lc + 1][lr] = pb0.y;
            Bs[nb][lc + 2][lr] = pb0.z; Bs[nb][lc + 3][lr] = pb0.w;
            Bs[nb][lc + 8][lr] = pb1.x; Bs[nb][lc + 9][lr] = pb1.y;
            Bs[nb][lc +10][lr] = pb1.z; Bs[nb][lc +11][lr] = pb1.w;
            __syncthreads();
            buf = nb;
        }
    }

#pragma unroll
    for (int ip = 0; ip < 4; ip++) {
        float lo[8], hi[8];
#pragma unroll
        for (int j = 0; j < 8; j++) upk2(acc2[ip][j], lo[j], hi[j]);
        float* C0 = C + (size_t)(bm + tm + 2 * ip) * N + bn + tn;
        float* C1 = C0 + N;
        *(float4*)(C0)     = make_float4(lo[0], lo[1], lo[2], lo[3]);
        *(float4*)(C0 + 4) = make_float4(lo[4], lo[5], lo[6], lo[7]);
        *(float4*)(C1)     = make_float4(hi[0], hi[1], hi[2], hi[3]);
        *(float4*)(C1 + 4) = make_float4(hi[4], hi[5], hi[6], hi[7]);
    }
}

// ---------------------------------------------------------------------------
// Flash attention v3 (fp32 f32x2, online softmax, causal tile skipping)
// Q/K/V/O viewed as [BH=32][S=2048][64] contiguous.
// BM=128 q-rows per CTA, BN=64 kv-rows per tile, 256 threads, 8x4 micro-tile
// (rows packed in f32x2 pairs).
// Shared layouts (all chosen so inner loops are LDS.64-pair / LDS.128 reads):
//   QT[d][m]  pitch 130 : q-pairs = LDS.64, broadcast, conflict-free
//   KT[d][n]  pitch 68  : k row = one LDS.128 per d
//   Vs[n][d]  pitch 68  : v row = one LDS.128 per n
//   PT[n][m]  pitch 130 : p-pairs = LDS.64; written as STS.64 pairs
// ---------------------------------------------------------------------------
#define BM 128
#define BN 64
#define QTP 130
#define KTP 68
#define VP  68
#define PTP 130
#define SM_QT (64 * QTP)
#define SM_KT (64 * KTP)
#define SM_VS (64 * VP)
#define SM_PT (64 * PTP)
#define FLASH_SMEM ((SM_QT + SM_KT + SM_VS + SM_PT) * 4)

__global__ __launch_bounds__(256)
void flash_attn(const float* __restrict__ Q, const float* __restrict__ K,
                const float* __restrict__ V, float* __restrict__ O,
                const int* __restrict__ maskflag)
{
    extern __shared__ float sm[];
    float* QT = sm;                 // [d][m]
    float* KT = QT + SM_QT;         // [d][n]
    float* Vs = KT + SM_KT;         // [n][d]
    float* PT = Vs + SM_VS;         // [n][m]

    const int tid = threadIdx.x;
    const int bh  = blockIdx.y;
    const int bx  = blockIdx.x;
    const int m0  = bx * BM;

    const float* Qb = Q + (size_t)bh * PS * PHD;
    const float* Kb = K + (size_t)bh * PS * PHD;
    const float* Vb = V + (size_t)bh * PS * PHD;
    float*       Ob = O + (size_t)bh * PS * PHD + (size_t)m0 * PHD;

    const int tm = (tid >> 4) * 8;   // 8 rows per thread (4 f32x2 pairs)
    const int tn = (tid & 15) * 4;   // 4 cols per thread

    // load Q tile (128x64) and transpose into QT[d][m]
    for (int t = tid; t < 2048; t += 256) {
        int r = t >> 4, c4 = (t & 15) << 2;
        float4 x = *(const float4*)(Qb + (size_t)(m0 + r) * PHD + c4);
        QT[(c4 + 0) * QTP + r] = x.x;
        QT[(c4 + 1) * QTP + r] = x.y;
        QT[(c4 + 2) * QTP + r] = x.z;
        QT[(c4 + 3) * QTP + r] = x.w;
    }

    const bool causal = (*maskflag != 0);
    const int ntiles = causal ? (2 * bx + 2) : (PS / BN);

    float mrow[8], lrow[8];
    ull o2[4][4];
#pragma unroll
    for (int i = 0; i < 8; i++) { mrow[i] = -1e30f; lrow[i] = 0.f; }
#pragma unroll
    for (int ip = 0; ip < 4; ip++)
#pragma unroll
        for (int j = 0; j < 4; j++) o2[ip][j] = 0ULL;

    for (int kt = 0; kt < ntiles; kt++) {
        const int n0 = kt * BN;

        // load K (transposed into KT) and V (direct) tiles
        for (int t = tid; t < 1024; t += 256) {
            int r = t >> 4, c4 = (t & 15) << 2;
            float4 xk = *(const float4*)(Kb + (size_t)(n0 + r) * PHD + c4);
            KT[(c4 + 0) * KTP + r] = xk.x;
            KT[(c4 + 1) * KTP + r] = xk.y;
            KT[(c4 + 2) * KTP + r] = xk.z;
            KT[(c4 + 3) * KTP + r] = xk.w;
            float4 xv = *(const float4*)(Vb + (size_t)(n0 + r) * PHD + c4);
            *(float4*)&Vs[r * VP + c4] = xv;
        }
        __syncthreads();   // K/V (and QT on first iter) ready

        // S = Q K^T  (8x4 per thread, rows packed in pairs)
        ull s2[4][4];
#pragma unroll
        for (int ip = 0; ip < 4; ip++)
#pragma unroll
            for (int j = 0; j < 4; j++) s2[ip][j] = 0ULL;

#pragma unroll 4
        for (int d = 0; d < 64; d++) {
            ull q2[4];
            q2[0] = *(const ull*)&QT[d * QTP + tm + 0];
            q2[1] = *(const ull*)&QT[d * QTP + tm + 2];
            q2[2] = *(const ull*)&QT[d * QTP + tm + 4];
            q2[3] = *(const ull*)&QT[d * QTP + tm + 6];
            float4 k4 = *(const float4*)&KT[d * KTP + tn];
            ull kd[4];
            kd[0] = pk2(k4.x, k4.x); kd[1] = pk2(k4.y, k4.y);
            kd[2] = pk2(k4.z, k4.z); kd[3] = pk2(k4.w, k4.w);
#pragma unroll
            for (int ip = 0; ip < 4; ip++)
#pragma unroll
                for (int j = 0; j < 4; j++)
                    s2[ip][j] = ffma2(q2[ip], kd[j], s2[ip][j]);
        }

        const float scale = 0.125f;  // 1/sqrt(64)
        const bool needMask = causal && (n0 + BN - 1 > m0);

        // online softmax per row-pair; write P^T pairs; rescale O
#pragma unroll
        for (int ip = 0; ip < 4; ip++) {
            float sl[4], sh[4];
#pragma unroll
            for (int j = 0; j < 4; j++) {
                upk2(s2[ip][j], sl[j], sh[j]);
                sl[j] *= scale; sh[j] *= scale;
            }
            const int r0 = m0 + tm + 2 * ip;
            if (needMask) {
#pragma unroll
                for (int j = 0; j < 4; j++) {
                    int col = n0 + tn + j;
                    if (col > r0)     sl[j] = -1e30f;
                    if (col > r0 + 1) sh[j] = -1e30f;
                }
            }

            float alo, ahi;
            float plo[4], phi[4];
            {   // row lo (index 2ip)
                const int i = 2 * ip;
                float pm = fmaxf(fmaxf(sl[0], sl[1]), fmaxf(sl[2], sl[3]));
#pragma unroll
                for (int off = 8; off >= 1; off >>= 1)
                    pm = fmaxf(pm, __shfl_xor_sync(0xffffffffu, pm, off));
                float mnew = fmaxf(mrow[i], pm);
                alo = __expf(mrow[i] - mnew);
                float ps = 0.f;
#pragma unroll
                for (int j = 0; j < 4; j++) { plo[j] = __expf(sl[j] - mnew); ps += plo[j]; }
#pragma unroll
                for (int off = 8; off >= 1; off >>= 1)
                    ps += __shfl_xor_sync(0xffffffffu, ps, off);
                lrow[i] = lrow[i] * alo + ps;
                mrow[i] = mnew;
            }
            {   // row hi (index 2ip+1)
                const int i = 2 * ip + 1;
                float pm = fmaxf(fmaxf(sh[0], sh[1]), fmaxf(sh[2], sh[3]));
#pragma unroll
                for (int off = 8; off >= 1; off >>= 1)
                    pm = fmaxf(pm, __shfl_xor_sync(0xffffffffu, pm, off));
                float mnew = fmaxf(mrow[i], pm);
                ahi = __expf(mrow[i] - mnew);
                float ps = 0.f;
#pragma unroll
                for (int j = 0; j < 4; j++) { phi[j] = __expf(sh[j] - mnew); ps += phi[j]; }
#pragma unroll
                for (int off = 8; off >= 1; off >>= 1)
                    ps += __shfl_xor_sync(0xffffffffu, ps, off);
                lrow[i] = lrow[i] * ahi + ps;
                mrow[i] = mnew;
            }

            // P^T store: m-adjacent pair in one STS.64
#pragma unroll
            for (int j = 0; j < 4; j++)
                *(ull*)&PT[(tn + j) * PTP + tm + 2 * ip] = pk2(plo[j], phi[j]);

            ull a2 = pk2(alo, ahi);
#pragma unroll
            for (int j = 0; j < 4; j++) o2[ip][j] = fmul2(o2[ip][j], a2);
        }
        __syncthreads();   // PT visible

        // O += P @ V
#pragma unroll 4
        for (int n = 0; n < 64; n++) {
            ull p2[4];
            p2[0] = *(const ull*)&PT[n * PTP + tm + 0];
            p2[1] = *(const ull*)&PT[n * PTP + tm + 2];
            p2[2] = *(const ull*)&PT[n * PTP + tm + 4];
            p2[3] = *(const ull*)&PT[n * PTP + tm + 6];
            float4 v4 = *(const float4*)&Vs[n * VP + tn];
            ull vd[4];
            vd[0] = pk2(v4.x, v4.x); vd[1] = pk2(v4.y, v4.y);
            vd[2] = pk2(v4.z, v4.z); vd[3] = pk2(v4.w, v4.w);
#pragma unroll
            for (int ip = 0; ip < 4; ip++)
#pragma unroll
                for (int j = 0; j < 4; j++)
                    o2[ip][j] = ffma2(p2[ip], vd[j], o2[ip][j]);
        }
        __syncthreads();   // KT/Vs/PT free for next tile
    }

    // epilogue: normalize and store
#pragma unroll
    for (int ip = 0; ip < 4; ip++) {
        float lo[4], hi[4];
#pragma unroll
        for (int j = 0; j < 4; j++) upk2(o2[ip][j], lo[j], hi[j]);
        float inv0 = 1.0f / lrow[2 * ip];
        float inv1 = 1.0f / lrow[2 * ip + 1];
        float* O0 = Ob + (size_t)(tm + 2 * ip) * PHD + tn;
        float* O1 = O0 + PHD;
        *(float4*)O0 = make_float4(lo[0] * inv0, lo[1] * inv0, lo[2] * inv0, lo[3] * inv0);
        *(float4*)O1 = make_float4(hi[0] * inv1, hi[1] * inv1, hi[2] * inv1, hi[3] * inv1);
    }
}

// ---------------------------------------------------------------------------
// Launch
// ---------------------------------------------------------------------------
extern "C" void kernel_launch(void* const* d_in, const int* in_sizes, int n_in,
                              void* d_out, int out_size)
{
    const float* q  = (const float*)d_in[0];
    const float* k  = (const float*)d_in[1];
    const float* v  = (const float*)d_in[2];
    const float* wq = (const float*)d_in[3];
    const float* wk = (const float*)d_in[4];
    const float* wv = (const float*)d_in[5];
    const float* wo = (const float*)d_in[6];
    const int*   am = (const int*)d_in[7];
    float* out = (float*)d_out;

    float *qp, *kp, *vp, *ao;
    cudaGetSymbolAddress((void**)&qp, g_qp);
    cudaGetSymbolAddress((void**)&kp, g_kp);
    cudaGetSymbolAddress((void**)&vp, g_vp);
    cudaGetSymbolAddress((void**)&ao, g_ao);

    cudaFuncSetAttribute(flash_attn, cudaFuncAttributeMaxDynamicSharedMemorySize,
                         FLASH_SMEM);

    dim3 gGemm(PE / TN, PM / TM);   // (8, 32)
    sgemm_tn<<<gGemm, 256>>>(q, wq, qp, PM, PE, PE);
    sgemm_tn<<<gGemm, 256>>>(k, wk, kp, PM, PE, PE);
    sgemm_tn<<<gGemm, 256>>>(v, wv, vp, PM, PE, PE);

    dim3 gAttn(PS / BM, PBH);       // (16, 32)
    flash_attn<<<gAttn, 256, FLASH_SMEM>>>(qp, kp, vp, ao, am);

    sgemm_tn<<<gGemm, 256>>>(ao, wo, out, PM, PE, PE);
}

// round 5
// speedup vs baseline: 1.7603x; 1.5516x over previous
#include <cuda_runtime.h>
#include <cuda_bf16.h>
#include <math_constants.h>
#include <cstdint>

// Problem constants
#define PB 2
#define PS 2048
#define PE 1024
#define PH 16
#define PHD 64
#define PBH (PB * PH)        // 32
#define PM (PB * PS)         // 4096 rows for all projection GEMMs

typedef unsigned long long ull;

// ---------------------------------------------------------------------------
// helpers
// ---------------------------------------------------------------------------
__device__ __forceinline__ ull pk2(float x, float y) {
    ull r; asm("mov.b64 %0, {%1, %2};" : "=l"(r) : "f"(x), "f"(y)); return r;
}
__device__ __forceinline__ void upk2(ull v, float& x, float& y) {
    asm("mov.b64 {%0, %1}, %2;" : "=f"(x), "=f"(y) : "l"(v));
}
__device__ __forceinline__ ull ffma2(ull a, ull b, ull c) {
    ull d; asm("fma.rn.f32x2 %0, %1, %2, %3;" : "=l"(d) : "l"(a), "l"(b), "l"(c)); return d;
}
__device__ __forceinline__ ull fmul2(ull a, ull b) {
    ull d; asm("mul.rn.f32x2 %0, %1, %2;" : "=l"(d) : "l"(a), "l"(b)); return d;
}
__device__ __forceinline__ uint32_t f2tf32(float f) {
    uint32_t u; asm("cvt.rna.tf32.f32 %0, %1;" : "=r"(u) : "f"(f)); return u;
}
__device__ __forceinline__ void mma_tf32(float c[4], const uint32_t a[4], const uint32_t b[2]) {
    asm("mma.sync.aligned.m16n8k8.row.col.f32.tf32.tf32.f32 "
        "{%0,%1,%2,%3}, {%4,%5,%6,%7}, {%8,%9}, {%0,%1,%2,%3};"
        : "+f"(c[0]), "+f"(c[1]), "+f"(c[2]), "+f"(c[3])
        : "r"(a[0]), "r"(a[1]), "r"(a[2]), "r"(a[3]), "r"(b[0]), "r"(b[1]));
}

// ---------------------------------------------------------------------------
// Scratch (no cudaMalloc allowed)
// ---------------------------------------------------------------------------
__device__ float g_qp[PM * PE];
__device__ float g_kp[PM * PE];
__device__ float g_vp[PM * PE];
__device__ float g_ao[PM * PE];

// ---------------------------------------------------------------------------
// TF32 tensor-core GEMM: C[M,N] = A[M,K] @ B[N,K]^T  (torch Linear)
// CTA 128x128, 8 warps (2x4), warp tile 64x32, K-tile 32 (4 x k8 steps).
// smem pitch 36 floats -> fragment LDS conflict-free (bank = 4*(lane>>2)+(lane&3)).
// Optional z-batching: blockIdx.z selects (A,B,C) triple.
// ---------------------------------------------------------------------------
#define GP 36   // smem pitch (floats)

__global__ __launch_bounds__(256, 2)
void gemm_tf32(const float* __restrict__ A0, const float* __restrict__ B0, float* __restrict__ C0,
               const float* __restrict__ A1, const float* __restrict__ B1, float* __restrict__ C1,
               const float* __restrict__ A2, const float* __restrict__ B2, float* __restrict__ C2,
               int M, int N, int K)
{
    __shared__ uint32_t As[128 * GP];
    __shared__ uint32_t Bs[128 * GP];

    const float* A = A0; const float* B = B0; float* C = C0;
    if (blockIdx.z == 1) { A = A1; B = B1; C = C1; }
    else if (blockIdx.z == 2) { A = A2; B = B2; C = C2; }

    const int tid  = threadIdx.x;
    const int lane = tid & 31;
    const int warp = tid >> 5;
    const int wm   = warp >> 2;          // 0..1
    const int wn   = warp & 3;           // 0..3
    const int gr   = lane >> 2;          // 0..7
    const int cc   = lane & 3;           // 0..3

    const int bm = blockIdx.y * 128;
    const int bn = blockIdx.x * 128;

    // loader mapping: 16 consecutive floats per thread per matrix
    const int lr = tid >> 1;             // 0..127
    const int lq = (tid & 1) * 16;       // 0 or 16

    const float* Ap = A + (size_t)(bm + lr) * K + lq;
    const float* Bp = B + (size_t)(bn + lr) * K + lq;

    float acc[4][4][4];
#pragma unroll
    for (int mt = 0; mt < 4; mt++)
#pragma unroll
        for (int nt = 0; nt < 4; nt++)
#pragma unroll
            for (int r = 0; r < 4; r++) acc[mt][nt][r] = 0.f;

    // prefetch tile 0
    float4 pa[4], pb[4];
#pragma unroll
    for (int i = 0; i < 4; i++) {
        pa[i] = *(const float4*)(Ap + i * 4);
        pb[i] = *(const float4*)(Bp + i * 4);
    }

    for (int k0 = 0; k0 < K; k0 += 32) {
        // store prefetched tile to smem (converted to tf32)
        uint32_t* Ad = &As[lr * GP + lq];
        uint32_t* Bd = &Bs[lr * GP + lq];
#pragma unroll
        for (int i = 0; i < 4; i++) {
            Ad[i * 4 + 0] = f2tf32(pa[i].x); Ad[i * 4 + 1] = f2tf32(pa[i].y);
            Ad[i * 4 + 2] = f2tf32(pa[i].z); Ad[i * 4 + 3] = f2tf32(pa[i].w);
            Bd[i * 4 + 0] = f2tf32(pb[i].x); Bd[i * 4 + 1] = f2tf32(pb[i].y);
            Bd[i * 4 + 2] = f2tf32(pb[i].z); Bd[i * 4 + 3] = f2tf32(pb[i].w);
        }
        __syncthreads();

        // prefetch next tile
        if (k0 + 32 < K) {
#pragma unroll
            for (int i = 0; i < 4; i++) {
                pa[i] = *(const float4*)(Ap + k0 + 32 + i * 4);
                pb[i] = *(const float4*)(Bp + k0 + 32 + i * 4);
            }
        }

#pragma unroll
        for (int ks = 0; ks < 4; ks++) {
            const int k8 = ks * 8;
            uint32_t afr[4][4], bfr[4][2];
#pragma unroll
            for (int mt = 0; mt < 4; mt++) {
                const int r0 = wm * 64 + mt * 16 + gr;
                afr[mt][0] = As[r0 * GP + k8 + cc];
                afr[mt][1] = As[(r0 + 8) * GP + k8 + cc];
                afr[mt][2] = As[r0 * GP + k8 + cc + 4];
                afr[mt][3] = As[(r0 + 8) * GP + k8 + cc + 4];
            }
#pragma unroll
            for (int nt = 0; nt < 4; nt++) {
                const int nr = wn * 32 + nt * 8 + gr;
                bfr[nt][0] = Bs[nr * GP + k8 + cc];
                bfr[nt][1] = Bs[nr * GP + k8 + cc + 4];
            }
#pragma unroll
            for (int mt = 0; mt < 4; mt++)
#pragma unroll
                for (int nt = 0; nt < 4; nt++)
                    mma_tf32(acc[mt][nt], afr[mt], bfr[nt]);
        }
        __syncthreads();
    }

    // epilogue
#pragma unroll
    for (int mt = 0; mt < 4; mt++) {
        const int r0 = bm + wm * 64 + mt * 16 + gr;
#pragma unroll
        for (int nt = 0; nt < 4; nt++) {
            const int cb = bn + wn * 32 + nt * 8 + 2 * cc;
            *(float2*)(C + (size_t)r0 * N + cb)       = make_float2(acc[mt][nt][0], acc[mt][nt][1]);
            *(float2*)(C + (size_t)(r0 + 8) * N + cb) = make_float2(acc[mt][nt][2], acc[mt][nt][3]);
        }
    }
}

// ---------------------------------------------------------------------------
// Flash attention (fp32 f32x2, online softmax, causal tile skipping)
// (unchanged from R4 best: 673us)
// ---------------------------------------------------------------------------
#define BM 128
#define BN 64
#define QTP 130
#define KTP 68
#define VP  68
#define PTP 130
#define SM_QT (64 * QTP)
#define SM_KT (64 * KTP)
#define SM_VS (64 * VP)
#define SM_PT (64 * PTP)
#define FLASH_SMEM ((SM_QT + SM_KT + SM_VS + SM_PT) * 4)

__global__ __launch_bounds__(256)
void flash_attn(const float* __restrict__ Q, const float* __restrict__ K,
                const float* __restrict__ V, float* __restrict__ O,
                const int* __restrict__ maskflag)
{
    extern __shared__ float sm[];
    float* QT = sm;                 // [d][m]
    float* KT = QT + SM_QT;         // [d][n]
    float* Vs = KT + SM_KT;         // [n][d]
    float* PT = Vs + SM_VS;         // [n][m]

    const int tid = threadIdx.x;
    const int bh  = blockIdx.y;
    const int bx  = blockIdx.x;
    const int m0  = bx * BM;

    const float* Qb = Q + (size_t)bh * PS * PHD;
    const float* Kb = K + (size_t)bh * PS * PHD;
    const float* Vb = V + (size_t)bh * PS * PHD;
    float*       Ob = O + (size_t)bh * PS * PHD + (size_t)m0 * PHD;

    const int tm = (tid >> 4) * 8;   // 8 rows per thread (4 f32x2 pairs)
    const int tn = (tid & 15) * 4;   // 4 cols per thread

    for (int t = tid; t < 2048; t += 256) {
        int r = t >> 4, c4 = (t & 15) << 2;
        float4 x = *(const float4*)(Qb + (size_t)(m0 + r) * PHD + c4);
        QT[(c4 + 0) * QTP + r] = x.x;
        QT[(c4 + 1) * QTP + r] = x.y;
        QT[(c4 + 2) * QTP + r] = x.z;
        QT[(c4 + 3) * QTP + r] = x.w;
    }

    const bool causal = (*maskflag != 0);
    const int ntiles = causal ? (2 * bx + 2) : (PS / BN);

    float mrow[8], lrow[8];
    ull o2[4][4];
#pragma unroll
    for (int i = 0; i < 8; i++) { mrow[i] = -1e30f; lrow[i] = 0.f; }
#pragma unroll
    for (int ip = 0; ip < 4; ip++)
#pragma unroll
        for (int j = 0; j < 4; j++) o2[ip][j] = 0ULL;

    for (int kt = 0; kt < ntiles; kt++) {
        const int n0 = kt * BN;

        for (int t = tid; t < 1024; t += 256) {
            int r = t >> 4, c4 = (t & 15) << 2;
            float4 xk = *(const float4*)(Kb + (size_t)(n0 + r) * PHD + c4);
            KT[(c4 + 0) * KTP + r] = xk.x;
            KT[(c4 + 1) * KTP + r] = xk.y;
            KT[(c4 + 2) * KTP + r] = xk.z;
            KT[(c4 + 3) * KTP + r] = xk.w;
            float4 xv = *(const float4*)(Vb + (size_t)(n0 + r) * PHD + c4);
            *(float4*)&Vs[r * VP + c4] = xv;
        }
        __syncthreads();

        ull s2[4][4];
#pragma unroll
        for (int ip = 0; ip < 4; ip++)
#pragma unroll
            for (int j = 0; j < 4; j++) s2[ip][j] = 0ULL;

#pragma unroll 4
        for (int d = 0; d < 64; d++) {
            ull q2[4];
            q2[0] = *(const ull*)&QT[d * QTP + tm + 0];
            q2[1] = *(const ull*)&QT[d * QTP + tm + 2];
            q2[2] = *(const ull*)&QT[d * QTP + tm + 4];
            q2[3] = *(const ull*)&QT[d * QTP + tm + 6];
            float4 k4 = *(const float4*)&KT[d * KTP + tn];
            ull kd[4];
            kd[0] = pk2(k4.x, k4.x); kd[1] = pk2(k4.y, k4.y);
            kd[2] = pk2(k4.z, k4.z); kd[3] = pk2(k4.w, k4.w);
#pragma unroll
            for (int ip = 0; ip < 4; ip++)
#pragma unroll
                for (int j = 0; j < 4; j++)
                    s2[ip][j] = ffma2(q2[ip], kd[j], s2[ip][j]);
        }

        const float scale = 0.125f;
        const bool needMask = causal && (n0 + BN - 1 > m0);

#pragma unroll
        for (int ip = 0; ip < 4; ip++) {
            float sl[4], sh[4];
#pragma unroll
            for (int j = 0; j < 4; j++) {
                upk2(s2[ip][j], sl[j], sh[j]);
                sl[j] *= scale; sh[j] *= scale;
            }
            const int r0 = m0 + tm + 2 * ip;
            if (needMask) {
#pragma unroll
                for (int j = 0; j < 4; j++) {
                    int col = n0 + tn + j;
                    if (col > r0)     sl[j] = -1e30f;
                    if (col > r0 + 1) sh[j] = -1e30f;
                }
            }

            float alo, ahi;
            float plo[4], phi[4];
            {
                const int i = 2 * ip;
                float pm = fmaxf(fmaxf(sl[0], sl[1]), fmaxf(sl[2], sl[3]));
#pragma unroll
                for (int off = 8; off >= 1; off >>= 1)
                    pm = fmaxf(pm, __shfl_xor_sync(0xffffffffu, pm, off));
                float mnew = fmaxf(mrow[i], pm);
                alo = __expf(mrow[i] - mnew);
                float ps = 0.f;
#pragma unroll
                for (int j = 0; j < 4; j++) { plo[j] = __expf(sl[j] - mnew); ps += plo[j]; }
#pragma unroll
                for (int off = 8; off >= 1; off >>= 1)
                    ps += __shfl_xor_sync(0xffffffffu, ps, off);
                lrow[i] = lrow[i] * alo + ps;
                mrow[i] = mnew;
            }
            {
                const int i = 2 * ip + 1;
                float pm = fmaxf(fmaxf(sh[0], sh[1]), fmaxf(sh[2], sh[3]));
#pragma unroll
                for (int off = 8; off >= 1; off >>= 1)
                    pm = fmaxf(pm, __shfl_xor_sync(0xffffffffu, pm, off));
                float mnew = fmaxf(mrow[i], pm);
                ahi = __expf(mrow[i] - mnew);
                float ps = 0.f;
#pragma unroll
                for (int j = 0; j < 4; j++) { phi[j] = __expf(sh[j] - mnew); ps += phi[j]; }
#pragma unroll
                for (int off = 8; off >= 1; off >>= 1)
                    ps += __shfl_xor_sync(0xffffffffu, ps, off);
                lrow[i] = lrow[i] * ahi + ps;
                mrow[i] = mnew;
            }

#pragma unroll
            for (int j = 0; j < 4; j++)
                *(ull*)&PT[(tn + j) * PTP + tm + 2 * ip] = pk2(plo[j], phi[j]);

            ull a2 = pk2(alo, ahi);
#pragma unroll
            for (int j = 0; j < 4; j++) o2[ip][j] = fmul2(o2[ip][j], a2);
        }
        __syncthreads();

#pragma unroll 4
        for (int n = 0; n < 64; n++) {
            ull p2[4];
            p2[0] = *(const ull*)&PT[n * PTP + tm + 0];
            p2[1] = *(const ull*)&PT[n * PTP + tm + 2];
            p2[2] = *(const ull*)&PT[n * PTP + tm + 4];
            p2[3] = *(const ull*)&PT[n * PTP + tm + 6];
            float4 v4 = *(const float4*)&Vs[n * VP + tn];
            ull vd[4];
            vd[0] = pk2(v4.x, v4.x); vd[1] = pk2(v4.y, v4.y);
            vd[2] = pk2(v4.z, v4.z); vd[3] = pk2(v4.w, v4.w);
#pragma unroll
            for (int ip = 0; ip < 4; ip++)
#pragma unroll
                for (int j = 0; j < 4; j++)
                    o2[ip][j] = ffma2(p2[ip], vd[j], o2[ip][j]);
        }
        __syncthreads();
    }

#pragma unroll
    for (int ip = 0; ip < 4; ip++) {
        float lo[4], hi[4];
#pragma unroll
        for (int j = 0; j < 4; j++) upk2(o2[ip][j], lo[j], hi[j]);
        float inv0 = 1.0f / lrow[2 * ip];
        float inv1 = 1.0f / lrow[2 * ip + 1];
        float* O0 = Ob + (size_t)(tm + 2 * ip) * PHD + tn;
        float* O1 = O0 + PHD;
        *(float4*)O0 = make_float4(lo[0] * inv0, lo[1] * inv0, lo[2] * inv0, lo[3] * inv0);
        *(float4*)O1 = make_float4(hi[0] * inv1, hi[1] * inv1, hi[2] * inv1, hi[3] * inv1);
    }
}

// ---------------------------------------------------------------------------
// Launch
// ---------------------------------------------------------------------------
extern "C" void kernel_launch(void* const* d_in, const int* in_sizes, int n_in,
                              void* d_out, int out_size)
{
    const float* q  = (const float*)d_in[0];
    const float* k  = (const float*)d_in[1];
    const float* v  = (const float*)d_in[2];
    const float* wq = (const float*)d_in[3];
    const float* wk = (const float*)d_in[4];
    const float* wv = (const float*)d_in[5];
    const float* wo = (const float*)d_in[6];
    const int*   am = (const int*)d_in[7];
    float* out = (float*)d_out;

    float *qp, *kp, *vp, *ao;
    cudaGetSymbolAddress((void**)&qp, g_qp);
    cudaGetSymbolAddress((void**)&kp, g_kp);
    cudaGetSymbolAddress((void**)&vp, g_vp);
    cudaGetSymbolAddress((void**)&ao, g_ao);

    cudaFuncSetAttribute(flash_attn, cudaFuncAttributeMaxDynamicSharedMemorySize,
                         FLASH_SMEM);

    // fused Q/K/V projections (z = 0,1,2)
    dim3 gQKV(PE / 128, PM / 128, 3);   // (8, 32, 3)
    gemm_tf32<<<gQKV, 256>>>(q, wq, qp,  k, wk, kp,  v, wv, vp, PM, PE, PE);

    dim3 gAttn(PS / BM, PBH);           // (16, 32)
    flash_attn<<<gAttn, 256, FLASH_SMEM>>>(qp, kp, vp, ao, am);

    // output projection
    dim3 gO(PE / 128, PM / 128, 1);
    gemm_tf32<<<gO, 256>>>(ao, wo, out,  ao, wo, out,  ao, wo, out, PM, PE, PE);
}

// round 6
// speedup vs baseline: 2.9568x; 1.6797x over previous
#include <cuda_runtime.h>
#include <cuda_bf16.h>
#include <math_constants.h>
#include <cstdint>

// Problem constants
#define PB 2
#define PS 2048
#define PE 1024
#define PH 16
#define PHD 64
#define PBH (PB * PH)        // 32
#define PM (PB * PS)         // 4096

// ---------------------------------------------------------------------------
// helpers
// ---------------------------------------------------------------------------
__device__ __forceinline__ uint32_t f2tf32(float f) {
    uint32_t u; asm("cvt.rna.tf32.f32 %0, %1;" : "=r"(u) : "f"(f)); return u;
}
__device__ __forceinline__ void mma_tf32(float c[4], const uint32_t a[4], const uint32_t b[2]) {
    asm("mma.sync.aligned.m16n8k8.row.col.f32.tf32.tf32.f32 "
        "{%0,%1,%2,%3}, {%4,%5,%6,%7}, {%8,%9}, {%0,%1,%2,%3};"
        : "+f"(c[0]), "+f"(c[1]), "+f"(c[2]), "+f"(c[3])
        : "r"(a[0]), "r"(a[1]), "r"(a[2]), "r"(a[3]), "r"(b[0]), "r"(b[1]));
}

// ---------------------------------------------------------------------------
// Scratch (no cudaMalloc allowed)
// ---------------------------------------------------------------------------
__device__ float g_qp[PM * PE];
__device__ float g_kp[PM * PE];
__device__ float g_vp[PM * PE];
__device__ float g_ao[PM * PE];

// ---------------------------------------------------------------------------
// TF32 tensor-core GEMM: C[M,N] = A[M,K] @ B[N,K]^T  (torch Linear)
// CTA 128x128, 8 warps (2x4), warp tile 64x32, K-tile 32.
// (unchanged from R5: ~90us per GEMM)
// ---------------------------------------------------------------------------
#define GP 36   // smem pitch (floats)

__global__ __launch_bounds__(256, 2)
void gemm_tf32(const float* __restrict__ A0, const float* __restrict__ B0, float* __restrict__ C0,
               const float* __restrict__ A1, const float* __restrict__ B1, float* __restrict__ C1,
               const float* __restrict__ A2, const float* __restrict__ B2, float* __restrict__ C2,
               int M, int N, int K)
{
    __shared__ uint32_t As[128 * GP];
    __shared__ uint32_t Bs[128 * GP];

    const float* A = A0; const float* B = B0; float* C = C0;
    if (blockIdx.z == 1) { A = A1; B = B1; C = C1; }
    else if (blockIdx.z == 2) { A = A2; B = B2; C = C2; }

    const int tid  = threadIdx.x;
    const int lane = tid & 31;
    const int warp = tid >> 5;
    const int wm   = warp >> 2;          // 0..1
    const int wn   = warp & 3;           // 0..3
    const int gr   = lane >> 2;          // 0..7
    const int cc   = lane & 3;           // 0..3

    const int bm = blockIdx.y * 128;
    const int bn = blockIdx.x * 128;

    const int lr = tid >> 1;             // 0..127
    const int lq = (tid & 1) * 16;       // 0 or 16

    const float* Ap = A + (size_t)(bm + lr) * K + lq;
    const float* Bp = B + (size_t)(bn + lr) * K + lq;

    float acc[4][4][4];
#pragma unroll
    for (int mt = 0; mt < 4; mt++)
#pragma unroll
        for (int nt = 0; nt < 4; nt++)
#pragma unroll
            for (int r = 0; r < 4; r++) acc[mt][nt][r] = 0.f;

    float4 pa[4], pb[4];
#pragma unroll
    for (int i = 0; i < 4; i++) {
        pa[i] = *(const float4*)(Ap + i * 4);
        pb[i] = *(const float4*)(Bp + i * 4);
    }

    for (int k0 = 0; k0 < K; k0 += 32) {
        uint32_t* Ad = &As[lr * GP + lq];
        uint32_t* Bd = &Bs[lr * GP + lq];
#pragma unroll
        for (int i = 0; i < 4; i++) {
            Ad[i * 4 + 0] = f2tf32(pa[i].x); Ad[i * 4 + 1] = f2tf32(pa[i].y);
            Ad[i * 4 + 2] = f2tf32(pa[i].z); Ad[i * 4 + 3] = f2tf32(pa[i].w);
            Bd[i * 4 + 0] = f2tf32(pb[i].x); Bd[i * 4 + 1] = f2tf32(pb[i].y);
            Bd[i * 4 + 2] = f2tf32(pb[i].z); Bd[i * 4 + 3] = f2tf32(pb[i].w);
        }
        __syncthreads();

        if (k0 + 32 < K) {
#pragma unroll
            for (int i = 0; i < 4; i++) {
                pa[i] = *(const float4*)(Ap + k0 + 32 + i * 4);
                pb[i] = *(const float4*)(Bp + k0 + 32 + i * 4);
            }
        }

#pragma unroll
        for (int ks = 0; ks < 4; ks++) {
            const int k8 = ks * 8;
            uint32_t afr[4][4], bfr[4][2];
#pragma unroll
            for (int mt = 0; mt < 4; mt++) {
                const int r0 = wm * 64 + mt * 16 + gr;
                afr[mt][0] = As[r0 * GP + k8 + cc];
                afr[mt][1] = As[(r0 + 8) * GP + k8 + cc];
                afr[mt][2] = As[r0 * GP + k8 + cc + 4];
                afr[mt][3] = As[(r0 + 8) * GP + k8 + cc + 4];
            }
#pragma unroll
            for (int nt = 0; nt < 4; nt++) {
                const int nr = wn * 32 + nt * 8 + gr;
                bfr[nt][0] = Bs[nr * GP + k8 + cc];
                bfr[nt][1] = Bs[nr * GP + k8 + cc + 4];
            }
#pragma unroll
            for (int mt = 0; mt < 4; mt++)
#pragma unroll
                for (int nt = 0; nt < 4; nt++)
                    mma_tf32(acc[mt][nt], afr[mt], bfr[nt]);
        }
        __syncthreads();
    }

#pragma unroll
    for (int mt = 0; mt < 4; mt++) {
        const int r0 = bm + wm * 64 + mt * 16 + gr;
#pragma unroll
        for (int nt = 0; nt < 4; nt++) {
            const int cb = bn + wn * 32 + nt * 8 + 2 * cc;
            *(float2*)(C + (size_t)r0 * N + cb)       = make_float2(acc[mt][nt][0], acc[mt][nt][1]);
            *(float2*)(C + (size_t)(r0 + 8) * N + cb) = make_float2(acc[mt][nt][2], acc[mt][nt][3]);
        }
    }
}

// ---------------------------------------------------------------------------
// Flash attention, tf32 tensor cores.
// Q/K/V/O viewed as [BH=32][S=2048][64] contiguous.
// CTA: BM=128 q-rows, 8 warps; warp owns 16 COMPLETE rows (warp tile 16x64)
// -> softmax entirely warp-local. BN=64 kv per tile.
// smem: Ks[64][68] (K rows, pitch 68: b-frag bank = 4*gr+cc, conflict-free)
//       Vs[64][72] (V rows untransposed, pitch 72: PV b-frag bank = 8(cc+nt)+gr)
//       Ps[128][68] (P rows, warp-private; also used to stage Q at start)
// Q fragments persistent in registers (scaled by 1/8, tf32).
// ---------------------------------------------------------------------------
#define KSP 68
#define VSP 72
#define PSP 68
#define SM_KS (64 * KSP)
#define SM_VS (64 * VSP)
#define SM_PS (128 * PSP)
#define FLASH_SMEM ((SM_KS + SM_VS + SM_PS) * 4)

__global__ __launch_bounds__(256, 2)
void flash_tc(const float* __restrict__ Q, const float* __restrict__ K,
              const float* __restrict__ V, float* __restrict__ O,
              const int* __restrict__ maskflag)
{
    extern __shared__ float smf[];
    float* Ks = smf;                 // [n][d] pitch 68
    float* Vs = Ks + SM_KS;          // [n][d] pitch 72
    float* Ps = Vs + SM_VS;          // [m][n] pitch 68 (Q staging first)

    const int tid  = threadIdx.x;
    const int lane = tid & 31;
    const int warp = tid >> 5;
    const int gr   = lane >> 2;      // 0..7
    const int cc   = lane & 3;       // 0..3
    const int bh   = blockIdx.y;
    const int bx   = blockIdx.x;
    const int m0   = bx * 128;
    const int wr0  = warp * 16;      // warp's row base within tile

    const float* Qb = Q + (size_t)bh * PS * PHD;
    const float* Kb = K + (size_t)bh * PS * PHD;
    const float* Vb = V + (size_t)bh * PS * PHD;
    float*       Ob = O + (size_t)bh * PS * PHD + (size_t)m0 * PHD;

    // ---- stage Q (scaled) into Ps, then extract persistent tf32 fragments ----
    for (int t = tid; t < 2048; t += 256) {
        int r = t >> 4, c4 = (t & 15) << 2;
        float4 x = *(const float4*)(Qb + (size_t)(m0 + r) * PHD + c4);
        float* d = &Ps[r * PSP + c4];
        d[0] = x.x * 0.125f; d[1] = x.y * 0.125f;
        d[2] = x.z * 0.125f; d[3] = x.w * 0.125f;
    }
    __syncthreads();

    uint32_t qa[8][4];
#pragma unroll
    for (int s = 0; s < 8; s++) {
        const int k8 = s * 8;
        qa[s][0] = f2tf32(Ps[(wr0 + gr) * PSP + k8 + cc]);
        qa[s][1] = f2tf32(Ps[(wr0 + gr + 8) * PSP + k8 + cc]);
        qa[s][2] = f2tf32(Ps[(wr0 + gr) * PSP + k8 + cc + 4]);
        qa[s][3] = f2tf32(Ps[(wr0 + gr + 8) * PSP + k8 + cc + 4]);
    }
    __syncwarp();   // warp's Q rows consumed before this warp overwrites them with P

    const bool causal = (*maskflag != 0);
    const int ntiles = causal ? (2 * bx + 2) : (PS / 64);

    float mr0 = -1e30f, mr1 = -1e30f, lr0 = 0.f, lr1 = 0.f;
    float o[8][4];
#pragma unroll
    for (int nt = 0; nt < 8; nt++)
#pragma unroll
        for (int r = 0; r < 4; r++) o[nt][r] = 0.f;

    for (int kt = 0; kt < ntiles; kt++) {
        const int n0 = kt * 64;

        // cooperative K/V tile load (cvt to tf32 at store)
        for (int t = tid; t < 1024; t += 256) {
            int r = t >> 4, c4 = (t & 15) << 2;
            float4 xk = *(const float4*)(Kb + (size_t)(n0 + r) * PHD + c4);
            float* kd = &Ks[r * KSP + c4];
            kd[0] = __uint_as_float(f2tf32(xk.x)); kd[1] = __uint_as_float(f2tf32(xk.y));
            kd[2] = __uint_as_float(f2tf32(xk.z)); kd[3] = __uint_as_float(f2tf32(xk.w));
            float4 xv = *(const float4*)(Vb + (size_t)(n0 + r) * PHD + c4);
            float* vd = &Vs[r * VSP + c4];
            vd[0] = __uint_as_float(f2tf32(xv.x)); vd[1] = __uint_as_float(f2tf32(xv.y));
            vd[2] = __uint_as_float(f2tf32(xv.z)); vd[3] = __uint_as_float(f2tf32(xv.w));
        }
        __syncthreads();

        // ---- S = Q K^T : warp computes 16 rows x 64 cols ----
        float s[8][4];
#pragma unroll
        for (int nt = 0; nt < 8; nt++)
#pragma unroll
            for (int r = 0; r < 4; r++) s[nt][r] = 0.f;

#pragma unroll
        for (int ks = 0; ks < 8; ks++) {
            const int k8 = ks * 8;
#pragma unroll
            for (int nt = 0; nt < 8; nt++) {
                uint32_t b[2];
                b[0] = __float_as_uint(Ks[(nt * 8 + gr) * KSP + k8 + cc]);
                b[1] = __float_as_uint(Ks[(nt * 8 + gr) * KSP + k8 + cc + 4]);
                mma_tf32(s[nt], qa[ks], b);
            }
        }

        // ---- causal mask ----
        const int rlo = m0 + wr0 + gr;
        const int rhi = rlo + 8;
        if (causal && (n0 + 63 > rlo)) {
#pragma unroll
            for (int nt = 0; nt < 8; nt++) {
                const int c0 = n0 + nt * 8 + 2 * cc;
                if (c0 > rlo)     s[nt][0] = -1e30f;
                if (c0 + 1 > rlo) s[nt][1] = -1e30f;
                if (c0 > rhi)     s[nt][2] = -1e30f;
                if (c0 + 1 > rhi) s[nt][3] = -1e30f;
            }
        }

        // ---- online softmax (warp-local; quad = lanes sharing gr) ----
        float tl = -1e30f, th = -1e30f;
#pragma unroll
        for (int nt = 0; nt < 8; nt++) {
            tl = fmaxf(tl, fmaxf(s[nt][0], s[nt][1]));
            th = fmaxf(th, fmaxf(s[nt][2], s[nt][3]));
        }
        tl = fmaxf(tl, __shfl_xor_sync(0xffffffffu, tl, 1));
        tl = fmaxf(tl, __shfl_xor_sync(0xffffffffu, tl, 2));
        th = fmaxf(th, __shfl_xor_sync(0xffffffffu, th, 1));
        th = fmaxf(th, __shfl_xor_sync(0xffffffffu, th, 2));

        const float mn0 = fmaxf(mr0, tl);
        const float mn1 = fmaxf(mr1, th);
        const float al0 = __expf(mr0 - mn0);
        const float al1 = __expf(mr1 - mn1);

        float sl = 0.f, sh = 0.f;
#pragma unroll
        for (int nt = 0; nt < 8; nt++) {
            float p0 = __expf(s[nt][0] - mn0);
            float p1 = __expf(s[nt][1] - mn0);
            float p2 = __expf(s[nt][2] - mn1);
            float p3 = __expf(s[nt][3] - mn1);
            sl += p0 + p1; sh += p2 + p3;
            uint2 w0 = make_uint2(f2tf32(p0), f2tf32(p1));
            uint2 w1 = make_uint2(f2tf32(p2), f2tf32(p3));
            *(uint2*)&Ps[(wr0 + gr) * PSP + nt * 8 + 2 * cc]     = w0;
            *(uint2*)&Ps[(wr0 + gr + 8) * PSP + nt * 8 + 2 * cc] = w1;
        }
        sl += __shfl_xor_sync(0xffffffffu, sl, 1);
        sl += __shfl_xor_sync(0xffffffffu, sl, 2);
        sh += __shfl_xor_sync(0xffffffffu, sh, 1);
        sh += __shfl_xor_sync(0xffffffffu, sh, 2);

        lr0 = lr0 * al0 + sl;
        lr1 = lr1 * al1 + sh;
        mr0 = mn0; mr1 = mn1;

#pragma unroll
        for (int nt = 0; nt < 8; nt++) {
            o[nt][0] *= al0; o[nt][1] *= al0;
            o[nt][2] *= al1; o[nt][3] *= al1;
        }
        __syncwarp();   // warp-private P rows visible to warp

        // ---- O += P V : A = P rows (warp-private), B = V^T via Vs[n][d] ----
#pragma unroll
        for (int ks = 0; ks < 8; ks++) {
            const int k8 = ks * 8;
            uint32_t a[4];
            a[0] = __float_as_uint(Ps[(wr0 + gr) * PSP + k8 + cc]);
            a[1] = __float_as_uint(Ps[(wr0 + gr + 8) * PSP + k8 + cc]);
            a[2] = __float_as_uint(Ps[(wr0 + gr) * PSP + k8 + cc + 4]);
            a[3] = __float_as_uint(Ps[(wr0 + gr + 8) * PSP + k8 + cc + 4]);
#pragma unroll
            for (int nt = 0; nt < 8; nt++) {
                uint32_t b[2];
                b[0] = __float_as_uint(Vs[(k8 + cc) * VSP + nt * 8 + gr]);
                b[1] = __float_as_uint(Vs[(k8 + cc + 4) * VSP + nt * 8 + gr]);
                mma_tf32(o[nt], a, b);
            }
        }
        __syncthreads();   // Ks/Vs consumed before next tile load
    }

    // ---- epilogue: normalize and store ----
    const float i0 = 1.0f / lr0;
    const float i1 = 1.0f / lr1;
#pragma unroll
    for (int nt = 0; nt < 8; nt++) {
        const int cb = nt * 8 + 2 * cc;
        *(float2*)(Ob + (size_t)(wr0 + gr) * PHD + cb) =
            make_float2(o[nt][0] * i0, o[nt][1] * i0);
        *(float2*)(Ob + (size_t)(wr0 + gr + 8) * PHD + cb) =
            make_float2(o[nt][2] * i1, o[nt][3] * i1);
    }
}

// ---------------------------------------------------------------------------
// Launch
// ---------------------------------------------------------------------------
extern "C" void kernel_launch(void* const* d_in, const int* in_sizes, int n_in,
                              void* d_out, int out_size)
{
    const float* q  = (const float*)d_in[0];
    const float* k  = (const float*)d_in[1];
    const float* v  = (const float*)d_in[2];
    const float* wq = (const float*)d_in[3];
    const float* wk = (const float*)d_in[4];
    const float* wv = (const float*)d_in[5];
    const float* wo = (const float*)d_in[6];
    const int*   am = (const int*)d_in[7];
    float* out = (float*)d_out;

    float *qp, *kp, *vp, *ao;
    cudaGetSymbolAddress((void**)&qp, g_qp);
    cudaGetSymbolAddress((void**)&kp, g_kp);
    cudaGetSymbolAddress((void**)&vp, g_vp);
    cudaGetSymbolAddress((void**)&ao, g_ao);

    cudaFuncSetAttribute(flash_tc, cudaFuncAttributeMaxDynamicSharedMemorySize,
                         FLASH_SMEM);

    // fused Q/K/V projections (z = 0,1,2)
    dim3 gQKV(PE / 128, PM / 128, 3);   // (8, 32, 3)
    gemm_tf32<<<gQKV, 256>>>(q, wq, qp,  k, wk, kp,  v, wv, vp, PM, PE, PE);

    dim3 gAttn(PS / 128, PBH);          // (16, 32)
    flash_tc<<<gAttn, 256, FLASH_SMEM>>>(qp, kp, vp, ao, am);

    // output projection
    dim3 gO(PE / 128, PM / 128, 1);
    gemm_tf32<<<gO, 256>>>(ao, wo, out,  ao, wo, out,  ao, wo, out, PM, PE, PE);
}